// round 17
// baseline (speedup 1.0000x reference)
#include <cuda_runtime.h>
#include <cuda_bf16.h>
#include <stdint.h>

// Problem constants
#define T_LEN   262144
#define A_DIM   64
#define ALPHA_F 0.99f
#define GAMMA_F 0.999f
#define LAMBD_F 0.7f

// Windowed scan: decay a_t <= gamma*lambda = 0.6993, so any suffix composite
// over >= 512 elements has A == +0 exactly in f32 (underflow: 0.6993^289 < 2^-149),
// killing the inter-chunk carry. Block scans 1024 window, outputs first 512.
#define OUT   512
#define WIN   1024
#define NWIN  (T_LEN / OUT)    // 512 blocks
#define K2T   512              // threads per block
#define ITEMS 2                // 512 threads * 2 = 1024 window
#define NWARP (K2T / 32)       // 16 warps

// ---------------- scratch (__device__ globals, no allocation) ----------------
__device__ float g_vpq [T_LEN];     // pi_t . q_t
__device__ float g_vpts[T_LEN];     // pi_{t+1} . q_tar_{t+1}  (SHIFTED: index t holds vpt[t+1])
__device__ float g_qta [T_LEN];     // q[t, a_t]
__device__ float g_rho [T_LEN];     // pi[t,a]/mu[t,a]

// combine(L, R) = L o R  (R applied to carry first):  a = aL*aR ; b = aL*bR + bL
__device__ __forceinline__ void comb(float& la, float& lb, float ra, float rb) {
    lb = fmaf(la, rb, lb);
    la = la * ra;
}

__device__ __forceinline__ float sel4(const float4 v, int c) {
    float r = v.x;
    if (c == 1) r = v.y;
    else if (c == 2) r = v.z;
    else if (c == 3) r = v.w;
    return r;
}

// ---------------- K1: per-row reductions + advantages ----------------
// 16 lanes per row (float4 per lane), 2 rows per warp. Rows 0..T inclusive.
// a_t and mu loads hoisted BEFORE the reduction to overlap their ~1100cyc
// serial latency with the shuffle tree. (Measured at DRAM roofline — frozen.)
__global__ void k1_rows(const float* __restrict__ q,
                        const float* __restrict__ q_tar,
                        const float* __restrict__ pi,
                        const float* __restrict__ mu,
                        const int*   __restrict__ a_t,
                        float* __restrict__ adv_out)   // = d_out + T_LEN
{
    const int warp = blockIdx.x * (blockDim.x >> 5) + (threadIdx.x >> 5);
    const int lane = threadIdx.x & 31;
    const int half = lane >> 4;            // 0 or 1
    const int sub  = lane & 15;            // lane within half
    const int row  = warp * 2 + half;      // rows 0 .. T_LEN inclusive
    if (row > T_LEN) {
        cudaTriggerProgrammaticLaunchCompletion();
        return;
    }
    const unsigned hm = 0xFFFFu << (half << 4);   // per-half shuffle mask
    const bool inner = (row < T_LEN);

    // issue action load first (independent of everything)
    int a = 0;
    if (inner) a = __ldg(a_t + row);

    const size_t base = (size_t)row * A_DIM;
    const float4 qv = __ldg(((const float4*)(q     + base)) + sub);
    const float4 pv = __ldg(((const float4*)(pi    + base)) + sub);
    const float4 tv = __ldg(((const float4*)(q_tar + base)) + sub);

    // mu load depends only on `a` — issue before reduction so it overlaps
    float muv = 1.0f;
    if (inner) muv = __ldg(mu + base + a);

    float s1 = pv.x * qv.x + pv.y * qv.y + pv.z * qv.z + pv.w * qv.w; // pi.q
    float s2 = pv.x * tv.x + pv.y * tv.y + pv.z * tv.z + pv.w * tv.w; // pi.q_tar
    #pragma unroll
    for (int o = 8; o; o >>= 1) {
        s1 += __shfl_xor_sync(hm, s1, o);
        s2 += __shfl_xor_sync(hm, s2, o);
    }

    if (inner) {
        const float v = s1;
        const float coef = 1.0f - ALPHA_F;     // 0.01
        float4 adv;
        adv.x = coef * (qv.x - v);
        adv.y = coef * (qv.y - v);
        adv.z = coef * (qv.z - v);
        adv.w = coef * (qv.w - v);
        ((float4*)(adv_out + base))[sub] = adv;

        const int comp = a & 3;                // a uniform within the half
        const int src  = (half << 4) + (a >> 2);
        float qcand = sel4(qv, comp);
        float pcand = sel4(pv, comp);
        float qa = __shfl_sync(hm, qcand, src);
        float pa = __shfl_sync(hm, pcand, src);
        if (sub == 0) {
            g_vpq[row] = s1;
            g_qta[row] = qa;
            g_rho[row] = pa / muv;
        }
    }
    if (sub == 0 && row > 0) g_vpts[row - 1] = s2;   // shifted store: vpts[t] = vpt[t+1]

    // PDL: all our global writes are done; let the dependent grid's sync release.
    cudaTriggerProgrammaticLaunchCompletion();
}

// ---------------- K2: windowed suffix scan, fully parallel -------------------
// Block B: window [B*OUT, B*OUT+WIN), outputs [B*OUT, B*OUT+OUT).
// 512 threads x 2 items: 16 warps/block -> 8192 resident warps (~86% occ)
// to hide load latency (R15 profile: occ 37%, issue 28% at 256 threads).
__global__ void __launch_bounds__(K2T)
k2_win(const float* __restrict__ r_t,
       const int*   __restrict__ done_t,
       float* __restrict__ targets)
{
    const int tid  = threadIdx.x;
    const int lane = tid & 31;
    const int w    = tid >> 5;                  // 0..15
    const int W    = blockIdx.x * OUT;          // window start
    const int gbase = W + tid * ITEMS;          // this thread's 2 elements
    const bool valid = (gbase + ITEMS - 1) < T_LEN;   // pair-aligned; all-or-none

    const float lg = (float)(0.7 * 0.999);      // LAMBD*GAMMA (python double -> f32)

    // ---- pre-sync: K1-independent loads overlap K1 execution ----
    int2   dn = make_int2(0, 0);
    float2 rv = make_float2(0.f, 0.f);
    if (valid) {
        dn = __ldg((const int2*)  (done_t + gbase));
        rv = __ldg((const float2*)(r_t    + gbase));
    }

    // ---- wait for K1's stores to be visible ----
    cudaGridDependencySynchronize();

    float aA[2], aB[2], eb[2];
    int   dArr[2];
    dArr[0] = dn.x; dArr[1] = dn.y;
    if (valid) {
        const float2 vp = *(const float2*)(g_vpts + gbase);
        const float2 qa = *(const float2*)(g_qta  + gbase);
        const float2 rh = *(const float2*)(g_rho  + gbase);

        const float rArr[2]  = {rv.x, rv.y};
        const float vpArr[2] = {vp.x, vp.y};
        const float qaArr[2] = {qa.x, qa.y};
        const float rhArr[2] = {rh.x, rh.y};

        #pragma unroll
        for (int i = 0; i < 2; i++) {
            const int   d   = dArr[i];
            const float est = rArr[i] + (d ? 0.0f : GAMMA_F) * vpArr[i];
            const float td  = est - qaArr[i];
            const float cc  = LAMBD_F * fminf(fmaxf(rhArr[i], 0.0f), 1.0f);
            aA[i] = d ? 0.0f : (GAMMA_F * cc);
            aB[i] = lg * rhArr[i] * td;
            eb[i] = est;   // + ALPHA*(qa - vpq) added below for output warps
        }
        if (w < NWARP / 2) {   // only output warps need vpq
            const float2 vq = *(const float2*)(g_vpq + gbase);
            eb[0] += ALPHA_F * (qaArr[0] - vq.x);
            eb[1] += ALPHA_F * (qaArr[1] - vq.y);
        }
    } else {
        #pragma unroll
        for (int i = 0; i < 2; i++) { aA[i] = 1.0f; aB[i] = 0.0f; eb[i] = 0.0f; dArr[i] = 0; }
    }

    // per-element exclusive suffix composites within the thread (element 1 = later t)
    float xa[2], xb[2];
    xa[1] = 1.0f;  xb[1] = 0.0f;
    xa[0] = aA[1]; xb[0] = aB[1];
    float ta = aA[0], tb = aB[0]; comb(ta, tb, xa[0], xb[0]);   // thread composite

    // warp inclusive suffix scan of thread composites (higher lane = later t)
    float ia = ta, ib = tb;
    #pragma unroll
    for (int off = 1; off < 32; off <<= 1) {
        float oa = __shfl_down_sync(0xffffffffu, ia, off);
        float ob = __shfl_down_sync(0xffffffffu, ib, off);
        if (lane + off < 32) comb(ia, ib, oa, ob);
    }
    // exclusive per-lane
    float ea  = __shfl_down_sync(0xffffffffu, ia, 1);
    float ebx = __shfl_down_sync(0xffffffffu, ib, 1);
    if (lane == 31) { ea = 1.0f; ebx = 0.0f; }

    __shared__ float swa[NWARP], swb[NWARP];
    if (lane == 0) { swa[w] = ia; swb[w] = ib; }   // warp composite = lane 0 inclusive
    __syncthreads();

    // exclusive suffix over warps: EW_w = W_{w+1} o ... o W_{15}
    float wa = 1.0f, wb = 0.0f;
    #pragma unroll
    for (int j = NWARP - 1; j >= 1; j--) {
        if (j > w) {
            float na = swa[j], nb = swb[j];
            comb(na, nb, wa, wb);    // acc = W_j o acc
            wa = na; wb = nb;
        }
    }

    if (w < NWARP / 2) {   // output region: elements [W, W+512)
        // full exclusive-within-window per element: X_i = e_i o E_lane o EW_w
        float fa = ea, fb = ebx;
        comb(fa, fb, wa, wb);
        #pragma unroll
        for (int i = 0; i < 2; i++) comb(xa[i], xb[i], fa, fb);

        // carry beyond window is annihilated (Xa == +0 exactly): y_in = Xb
        float2 o;
        o.x = eb[0] + (dArr[0] ? 0.0f : xb[0]);
        o.y = eb[1] + (dArr[1] ? 0.0f : xb[1]);
        *(float2*)(targets + gbase) = o;
    }
}

// ---------------- launch ----------------
extern "C" void kernel_launch(void* const* d_in, const int* in_sizes, int n_in,
                              void* d_out, int out_size)
{
    const float* q     = (const float*)d_in[0];   // (T+1, 64)
    const float* q_tar = (const float*)d_in[1];   // (T+1, 64)
    const float* pi    = (const float*)d_in[2];   // (T+1, 64)
    const int*   a_t   = (const int*)  d_in[3];   // (T,)
    const float* r_t   = (const float*)d_in[4];   // (T,)
    const float* mu_t  = (const float*)d_in[5];   // (T, 64)
    const int*   done  = (const int*)  d_in[6];   // (T,)

    float* out_targets = (float*)d_out;           // first T floats
    float* out_adv     = (float*)d_out + T_LEN;   // then T*64 floats

    // K1: 2 rows per warp, 8 warps per 256-thread block, rows = T+1
    {
        int rows  = T_LEN + 1;
        int warps = (rows + 1) / 2;
        int warps_per_blk = 8;
        int blocks = (warps + warps_per_blk - 1) / warps_per_blk;
        k1_rows<<<blocks, 256>>>(q, q_tar, pi, mu_t, a_t, out_adv);
    }
    // K2: PDL launch — overlaps its prologue (r_t/done_t loads) with K1's tail.
    {
        cudaLaunchAttribute attr[1];
        attr[0].id = cudaLaunchAttributeProgrammaticStreamSerialization;
        attr[0].val.programmaticStreamSerializationAllowed = 1;

        cudaLaunchConfig_t cfg = {};
        cfg.gridDim  = dim3(NWIN);
        cfg.blockDim = dim3(K2T);
        cfg.dynamicSmemBytes = 0;
        cfg.stream = 0;
        cfg.attrs = attr;
        cfg.numAttrs = 1;
        cudaLaunchKernelEx(&cfg, k2_win, r_t, done, out_targets);
    }
}